// round 6
// baseline (speedup 1.0000x reference)
#include <cuda_runtime.h>
#include <cuda_fp16.h>
#include <cstdint>

// LightGCN propagation on GB300 — round 6.
// out = (h0 + A h0 + A^2 h0 + A^3 h0)/4, A = D^-1/2 Adj D^-1/2 (COO), D=64.
//
// vs R5:
//  1. k_final no longer reads user/item: out = (0.25*rdinv)*(s0+s1+s2+s3),
//     exploiting rdinv*s0 == h0. 0.25 folded into stored rdinv.
//  2. k_hist / k_permute vectorized: 4 edges per thread via int4 loads.
//  3. k_final sums s-layers pairwise in fp16 (HADD2) before one fp32 scale.

#define DIM  64
#define NMAX 150002
#define EMAX 6400000

// prescaled layer buffers s0..s3, fp16 rows of 128B (8 uint4 per row)
__device__ uint4 g_s[4][(size_t)NMAX * 8];
__device__ float g_dinv[NMAX];    // (deg+eps)^-1/2
__device__ float g_rdinv[NMAX];   // 0.25*(deg+eps)^+1/2
__device__ int   g_deg[NMAX];
__device__ int   g_rowptr[NMAX + 1];
__device__ int   g_cursor[NMAX];
__device__ int   g_bsum[256];
__device__ int   g_pcol[EMAX];

// --- zero degree array --------------------------------------------------------
__global__ void k_zero(int n) {
    int i = blockIdx.x * blockDim.x + threadIdx.x;
    if (i < n) g_deg[i] = 0;
}

// --- degree histogram: 4 symmetric edge-pairs per thread -----------------------
__global__ void k_hist(const int4* __restrict__ rows4,
                       const int4* __restrict__ cols4, int E4,
                       const int* __restrict__ rows,
                       const int* __restrict__ cols, int E) {
    int i = blockIdx.x * blockDim.x + threadIdx.x;
    if (i < E4) {
        int4 r = __ldg(rows4 + i);
        int4 c = __ldg(cols4 + i);
        atomicAdd(&g_deg[r.x], 1); atomicAdd(&g_deg[c.x], 1);
        atomicAdd(&g_deg[r.y], 1); atomicAdd(&g_deg[c.y], 1);
        atomicAdd(&g_deg[r.z], 1); atomicAdd(&g_deg[c.z], 1);
        atomicAdd(&g_deg[r.w], 1); atomicAdd(&g_deg[c.w], 1);
    }
    // tail
    int t = E4 * 4 + i;
    if (i < E - E4 * 4) {
        atomicAdd(&g_deg[__ldg(rows + t)], 1);
        atomicAdd(&g_deg[__ldg(cols + t)], 1);
    }
}

// --- scan phase 1: per-block (1024) inclusive scan; block sums ----------------
__global__ void k_scan1(int n) {
    __shared__ int wsum[32];
    int tid = threadIdx.x, lane = tid & 31, wid = tid >> 5;
    int i = blockIdx.x * 1024 + tid;
    int v = (i < n) ? g_deg[i] : 0;
    int sv = v;
    #pragma unroll
    for (int d = 1; d < 32; d <<= 1) {
        int t = __shfl_up_sync(0xffffffffu, sv, d);
        if (lane >= d) sv += t;
    }
    if (lane == 31) wsum[wid] = sv;
    __syncthreads();
    if (wid == 0) {
        int w = wsum[lane];
        #pragma unroll
        for (int d = 1; d < 32; d <<= 1) {
            int t = __shfl_up_sync(0xffffffffu, w, d);
            if (lane >= d) w += t;
        }
        wsum[lane] = w;
    }
    __syncthreads();
    int incl = sv + ((wid > 0) ? wsum[wid - 1] : 0);
    if (i < n) g_rowptr[i + 1] = incl;
    if (tid == 1023) g_bsum[blockIdx.x] = incl;
}

// --- scan phase 2: exclusive scan of block sums --------------------------------
__global__ void k_scan2(int nb) {
    __shared__ int ws[8];
    int tid = threadIdx.x, lane = tid & 31, wid = tid >> 5;
    int v = (tid < nb) ? g_bsum[tid] : 0;
    int sv = v;
    #pragma unroll
    for (int d = 1; d < 32; d <<= 1) {
        int t = __shfl_up_sync(0xffffffffu, sv, d);
        if (lane >= d) sv += t;
    }
    if (lane == 31) ws[wid] = sv;
    __syncthreads();
    if (tid == 0) {
        int acc = 0;
        #pragma unroll
        for (int k = 0; k < 8; k++) { int t = ws[k]; ws[k] = acc; acc += t; }
    }
    __syncthreads();
    if (tid < nb) g_bsum[tid] = ws[wid] + sv - v;
}

// --- scan phase 3: apply offsets; emit rowptr/cursor/dinv/rdinv ---------------
__global__ void k_scan3(int n) {
    int i = blockIdx.x * blockDim.x + threadIdx.x;
    if (i >= n) return;
    int incl = g_rowptr[i + 1] + g_bsum[i >> 10];
    int v = g_deg[i];
    g_rowptr[i + 1] = incl;
    g_cursor[i]     = incl - v;
    float d = (float)v + 1e-7f;
    g_dinv[i]  = rsqrtf(d);
    g_rdinv[i] = 0.25f * sqrtf(d);
    if (i == 0) g_rowptr[0] = 0;
}

// --- init: s0 = half2(dinv .* h0), 16B per thread ------------------------------
__global__ void k_init(const float4* __restrict__ user,
                       const float4* __restrict__ item,
                       int u4, int n8) {
    int i = blockIdx.x * blockDim.x + threadIdx.x;
    if (i >= n8) return;
    int f4 = i * 2;
    float4 va, vb;
    if (f4 < u4) { va = __ldg(user + f4); vb = __ldg(user + f4 + 1); }
    else         { va = __ldg(item + (f4 - u4)); vb = __ldg(item + (f4 - u4) + 1); }
    float di = __ldg(&g_dinv[i >> 3]);
    __half2 h0 = __floats2half2_rn(di * va.x, di * va.y);
    __half2 h1 = __floats2half2_rn(di * va.z, di * va.w);
    __half2 h2 = __floats2half2_rn(di * vb.x, di * vb.y);
    __half2 h3 = __floats2half2_rn(di * vb.z, di * vb.w);
    uint4 o;
    o.x = *(const unsigned*)&h0; o.y = *(const unsigned*)&h1;
    o.z = *(const unsigned*)&h2; o.w = *(const unsigned*)&h3;
    g_s[0][i] = o;
}

// --- permute: 4 symmetric edge-pairs per thread --------------------------------
__global__ void k_permute(const int4* __restrict__ rows4,
                          const int4* __restrict__ cols4, int E4,
                          const int* __restrict__ rows,
                          const int* __restrict__ cols, int E) {
    int i = blockIdx.x * blockDim.x + threadIdx.x;
    if (i < E4) {
        int4 r = __ldg(rows4 + i);
        int4 c = __ldg(cols4 + i);
        int p;
        p = atomicAdd(&g_cursor[r.x], 1); g_pcol[p] = c.x;
        p = atomicAdd(&g_cursor[c.x], 1); g_pcol[p] = r.x;
        p = atomicAdd(&g_cursor[r.y], 1); g_pcol[p] = c.y;
        p = atomicAdd(&g_cursor[c.y], 1); g_pcol[p] = r.y;
        p = atomicAdd(&g_cursor[r.z], 1); g_pcol[p] = c.z;
        p = atomicAdd(&g_cursor[c.z], 1); g_pcol[p] = r.z;
        p = atomicAdd(&g_cursor[r.w], 1); g_pcol[p] = c.w;
        p = atomicAdd(&g_cursor[c.w], 1); g_pcol[p] = r.w;
    }
    int t = E4 * 4 + i;
    if (i < E - E4 * 4) {
        int r = __ldg(rows + t), c = __ldg(cols + t);
        int p;
        p = atomicAdd(&g_cursor[r], 1); g_pcol[p] = c;
        p = atomicAdd(&g_cursor[c], 1); g_pcol[p] = r;
    }
}

// --- gather SpMM: warp/row; quarter-warp 4-edge groups; LDG.128; HADD2 chunks --
__global__ void k_gather(const uint4* __restrict__ x,
                         uint4* __restrict__ y, int n) {
    int gw   = (blockIdx.x * blockDim.x + threadIdx.x) >> 5;
    int lane = threadIdx.x & 31;
    if (gw >= n) return;
    int s = __ldg(&g_rowptr[gw]);
    int e = __ldg(&g_rowptr[gw + 1]);
    int h = lane >> 3;          // edge-of-4 subgroup
    int q = lane & 7;           // 16B slice of the 128B row

    float a0 = 0.f, a1 = 0.f, a2 = 0.f, a3 = 0.f;
    float a4 = 0.f, a5 = 0.f, a6 = 0.f, a7 = 0.f;

    int base = s;
    int c = (base + 32 <= e) ? __ldg(&g_pcol[base + lane]) : 0;
    for (; base + 32 <= e; base += 32) {
        int c_cur = c;
        if (base + 64 <= e) c = __ldg(&g_pcol[base + 32 + lane]);

        __half2 z = __floats2half2_rn(0.f, 0.f);
        __half2 c0 = z, c1 = z, c2 = z, c3 = z;
        #pragma unroll
        for (int jj = 0; jj < 32; jj += 4) {
            int cj = __shfl_sync(0xffffffffu, c_cur, jj + h);
            uint4 r = __ldg(x + cj * 8 + q);
            c0 = __hadd2(c0, *(const __half2*)&r.x);
            c1 = __hadd2(c1, *(const __half2*)&r.y);
            c2 = __hadd2(c2, *(const __half2*)&r.z);
            c3 = __hadd2(c3, *(const __half2*)&r.w);
        }
        float2 f;
        f = __half22float2(c0); a0 += f.x; a1 += f.y;
        f = __half22float2(c1); a2 += f.x; a3 += f.y;
        f = __half22float2(c2); a4 += f.x; a5 += f.y;
        f = __half22float2(c3); a6 += f.x; a7 += f.y;
    }
    if (base < e) {
        int idx = base + lane;
        int ct = (idx < e) ? __ldg(&g_pcol[idx]) : 0;
        int m = e - base;
        for (int jj = 0; jj < m; jj += 4) {
            int src = jj + h;
            int cj = __shfl_sync(0xffffffffu, ct, src & 31);
            if (src < m) {
                uint4 r = __ldg(x + cj * 8 + q);
                float2 f;
                f = __half22float2(*(const __half2*)&r.x); a0 += f.x; a1 += f.y;
                f = __half22float2(*(const __half2*)&r.y); a2 += f.x; a3 += f.y;
                f = __half22float2(*(const __half2*)&r.z); a4 += f.x; a5 += f.y;
                f = __half22float2(*(const __half2*)&r.w); a6 += f.x; a7 += f.y;
            }
        }
    }

    #pragma unroll
    for (int d = 8; d <= 16; d <<= 1) {
        a0 += __shfl_xor_sync(0xffffffffu, a0, d);
        a1 += __shfl_xor_sync(0xffffffffu, a1, d);
        a2 += __shfl_xor_sync(0xffffffffu, a2, d);
        a3 += __shfl_xor_sync(0xffffffffu, a3, d);
        a4 += __shfl_xor_sync(0xffffffffu, a4, d);
        a5 += __shfl_xor_sync(0xffffffffu, a5, d);
        a6 += __shfl_xor_sync(0xffffffffu, a6, d);
        a7 += __shfl_xor_sync(0xffffffffu, a7, d);
    }

    if (h == 0) {
        float di = __ldg(&g_dinv[gw]);
        float di2 = di * di;
        __half2 o0 = __floats2half2_rn(di2 * a0, di2 * a1);
        __half2 o1 = __floats2half2_rn(di2 * a2, di2 * a3);
        __half2 o2 = __floats2half2_rn(di2 * a4, di2 * a5);
        __half2 o3 = __floats2half2_rn(di2 * a6, di2 * a7);
        uint4 o;
        o.x = *(const unsigned*)&o0; o.y = *(const unsigned*)&o1;
        o.z = *(const unsigned*)&o2; o.w = *(const unsigned*)&o3;
        y[gw * 8 + q] = o;
    }
}

// --- final: out = (0.25*rdinv)*(s0+s1+s2+s3) -----------------------------------
__global__ void k_final(float4* __restrict__ out, int n8) {
    int i = blockIdx.x * blockDim.x + threadIdx.x;   // uint4 index
    if (i >= n8) return;
    uint4 s0 = g_s[0][i], s1 = g_s[1][i], s2 = g_s[2][i], s3 = g_s[3][i];
    float rq = __ldg(&g_rdinv[i >> 3]);     // already includes 0.25

    float4 oa, ob;
    {
        __half2 t01 = __hadd2(*(const __half2*)&s0.x, *(const __half2*)&s1.x);
        __half2 t23 = __hadd2(*(const __half2*)&s2.x, *(const __half2*)&s3.x);
        __half2 t   = __hadd2(t01, t23);
        float2 f = __half22float2(t);
        oa.x = rq * f.x; oa.y = rq * f.y;
    }
    {
        __half2 t01 = __hadd2(*(const __half2*)&s0.y, *(const __half2*)&s1.y);
        __half2 t23 = __hadd2(*(const __half2*)&s2.y, *(const __half2*)&s3.y);
        __half2 t   = __hadd2(t01, t23);
        float2 f = __half22float2(t);
        oa.z = rq * f.x; oa.w = rq * f.y;
    }
    {
        __half2 t01 = __hadd2(*(const __half2*)&s0.z, *(const __half2*)&s1.z);
        __half2 t23 = __hadd2(*(const __half2*)&s2.z, *(const __half2*)&s3.z);
        __half2 t   = __hadd2(t01, t23);
        float2 f = __half22float2(t);
        ob.x = rq * f.x; ob.y = rq * f.y;
    }
    {
        __half2 t01 = __hadd2(*(const __half2*)&s0.w, *(const __half2*)&s1.w);
        __half2 t23 = __hadd2(*(const __half2*)&s2.w, *(const __half2*)&s3.w);
        __half2 t   = __hadd2(t01, t23);
        float2 f = __half22float2(t);
        ob.z = rq * f.x; ob.w = rq * f.y;
    }
    int f4 = i * 2;
    out[f4]     = oa;
    out[f4 + 1] = ob;
}

extern "C" void kernel_launch(void* const* d_in, const int* in_sizes, int n_in,
                              void* d_out, int out_size) {
    const float* user = (const float*)d_in[0];
    const float* item = (const float*)d_in[1];
    const int*   rows = (const int*)  d_in[2];
    const int*   cols = (const int*)  d_in[3];
    // d_in[4] (vals) unused: reconstructed from degrees.
    float* out = (float*)d_out;

    const int U = in_sizes[0] / DIM;
    const int I = in_sizes[1] / DIM;
    const int N = U + I;
    const int NNZ = in_sizes[2];
    const int E = NNZ / 2;          // symmetric COO
    const int E4 = E / 4;

    const int n8 = N * 8;
    const int u4 = U * 16;

    void* ps;
    cudaGetSymbolAddress(&ps, g_s);
    uint4* S0 = (uint4*)ps;
    uint4* S1 = S0 + (size_t)NMAX * 8;
    uint4* S2 = S1 + (size_t)NMAX * 8;
    uint4* S3 = S2 + (size_t)NMAX * 8;

    const int TB = 256;
    const int gridN  = (N + TB - 1) / TB;
    const int gridN8 = (n8 + TB - 1) / TB;
    const int gridE4 = (E4 + TB - 1) / TB;
    const int gridW  = (N * 32 + TB - 1) / TB;
    const int nb     = (N + 1023) / 1024;

    k_zero<<<gridN, TB>>>(N);
    k_hist<<<gridE4, TB>>>((const int4*)rows, (const int4*)cols, E4, rows, cols, E);
    k_scan1<<<nb, 1024>>>(N);
    k_scan2<<<1, 256>>>(nb);
    k_scan3<<<gridN, TB>>>(N);
    k_init<<<gridN8, TB>>>((const float4*)user, (const float4*)item, u4, n8);
    k_permute<<<gridE4, TB>>>((const int4*)rows, (const int4*)cols, E4, rows, cols, E);

    k_gather<<<gridW, TB>>>(S0, S1, N);
    k_gather<<<gridW, TB>>>(S1, S2, N);
    k_gather<<<gridW, TB>>>(S2, S3, N);

    k_final<<<gridN8, TB>>>((float4*)out, n8);
}